// round 9
// baseline (speedup 1.0000x reference)
#include <cuda_runtime.h>
#include <cuda_bf16.h>

#define EPS 1e-12f

// Adjacent pair (vrow[i], vrow[i+1]) via 8B-aligned LDG.64s.
// i even (50%): one load. i odd: two loads, 2 SELs. Never straddles a sector.
__device__ __forceinline__ float2 pair_ld64(const float* __restrict__ vrow, int i) {
    const float2* p = reinterpret_cast<const float2*>(vrow + (i & ~1));
    float2 q = __ldg(p);
    if (i & 1) {
        float2 q2 = __ldg(p + 1);
        q.x = q.y;
        q.y = q2.x;
    }
    return q;
}

__device__ __forceinline__ float eval_one(float x_t, float x_c, int a,
                                          const float* __restrict__ vals,
                                          const float* __restrict__ t_tbl,
                                          const float* __restrict__ c_tbl,
                                          const int*   __restrict__ dims)
{
    // dims gather (hot, keep cached)
    int2 d = __ldg(reinterpret_cast<const int2*>(dims) + a);
    int td = d.x, cd = d.y;

    if (td <= 0 || cd <= 0) return 0.0f;

    bool need_t = (td > 1);
    bool need_c = (cd > 1);

    // table gathers, predicated: a dim<=1 table never affects the result
    const float4* tt4 = reinterpret_cast<const float4*>(t_tbl) + 2 * a;
    const float4* ct4 = reinterpret_cast<const float4*>(c_tbl) + 2 * a;
    float4 tA = make_float4(0.f, 0.f, 0.f, 0.f), tB = tA;
    float4 cA = tA, cB = tA;
    if (need_t) { tA = __ldg(tt4); tB = __ldg(tt4 + 1); }
    if (need_c) { cA = __ldg(ct4); cB = __ldg(ct4 + 1); }

    float tv[8] = {tA.x, tA.y, tA.z, tA.w, tB.x, tB.y, tB.z, tB.w};
    float cv[8] = {cA.x, cA.y, cA.z, cA.w, cB.x, cB.y, cB.z, cB.w};

    // searchsorted side='right' = count of (tbl <= x); garbage harmless when
    // the table was skipped (clamp to max(dim-1,0)=0 kills it)
    int ss_t = 0, ss_c = 0;
    #pragma unroll
    for (int j = 0; j < 8; ++j) {
        ss_t += (tv[j] <= x_t) ? 1 : 0;
        ss_c += (cv[j] <= x_c) ? 1 : 0;
    }

    int max_t = max(td - 1, 0);
    int max_c = max(cd - 1, 0);
    // clamp(min=1) then clamp(max=dim-1), matching the reference order
    int t_hi = min(max(ss_t, 1), max_t);
    int c_hi = min(max(ss_c, 1), max_c);
    int t_lo = max(t_hi - 1, 0);
    int c_lo = max(c_hi - 1, 0);

    // register-resident breakpoint selection (SEL chains)
    float t0 = tv[0], t1 = tv[0], c0 = cv[0], c1 = cv[0];
    #pragma unroll
    for (int j = 1; j < 8; ++j) {
        if (t_lo == j) t0 = tv[j];
        if (t_hi == j) t1 = tv[j];
        if (c_lo == j) c0 = cv[j];
        if (c_hi == j) c1 = cv[j];
    }

    float ti = t1 - t0;
    float ci = c1 - c0;
    bool t_deg = fabsf(ti) < EPS;
    bool c_deg = fabsf(ci) < EPS;

    float xt = fminf(fmaxf(x_t, t0), t1);
    float xc = fminf(fmaxf(x_c, c0), c1);

    float ti_s = t_deg ? EPS : ti;
    float ci_s = c_deg ? EPS : ci;

    float ft = fminf(fmaxf((xt - t0) / ti_s, 0.0f), 1.0f);
    float fc = fminf(fmaxf((xc - c0) / ci_s, 0.0f), 1.0f);

    const float* vrow = vals + (size_t)a * 64;
    float res;

    if (need_t && need_c) {
        // 2D bilinear: corners are two adjacent pairs (c_hi=c_lo+1, t_hi=t_lo+1)
        int i00 = t_lo * cd + c_lo;
        float2 p0 = pair_ld64(vrow, i00);        // v00, v01
        float2 p1 = pair_ld64(vrow, i00 + cd);   // v10, v11
        float v00 = p0.x, v01 = p0.y, v10 = p1.x, v11 = p1.y;
        if (t_deg & c_deg) {
            res = v00;
        } else if (t_deg) {
            res = v00 + (v01 - v00) * fc;
        } else if (c_deg) {
            res = v00 + (v10 - v00) * ft;
        } else {
            float wa = (t1 - xt) * (c1 - xc);
            float wb = (t1 - xt) * (xc - c0);
            float wc = (xt - t0) * (c1 - xc);
            float wd = (xt - t0) * (xc - c0);
            res = (v00 * wa + v01 * wb + v10 * wc + v11 * wd) / (ti_s * ci_s);
        }
    } else {
        // unified 1D-trans / 1D-cap / scalar (replicates reference selects)
        int   i0 = t_lo + c_lo;                  // only one can be nonzero
        float f  = need_t ? (t_deg ? 0.0f : ft)
                          : (c_deg ? 0.0f : fc); // scalar: zeroed table -> deg -> 0
        float2 p = pair_ld64(vrow, i0);
        res = p.x + (p.y - p.x) * f;
    }
    return res;
}

__global__ __launch_bounds__(256)
void timing_prop_kernel(const float* __restrict__ x_t_arr,
                        const float* __restrict__ x_c_arr,
                        const int*   __restrict__ arc_idxs,
                        const float* __restrict__ vals,
                        const float* __restrict__ t_tbl,
                        const float* __restrict__ c_tbl,
                        const int*   __restrict__ dims,
                        float*       __restrict__ out,
                        int B)
{
    int i  = blockIdx.x * blockDim.x + threadIdx.x;
    int b0 = 2 * i;
    if (b0 >= B) return;

    if (b0 + 1 < B) {
        // vectorized streamed I/O (zero reuse -> evict-first)
        float2 xt2 = __ldcs(reinterpret_cast<const float2*>(x_t_arr) + i);
        float2 xc2 = __ldcs(reinterpret_cast<const float2*>(x_c_arr) + i);
        int2   a2  = __ldcs(reinterpret_cast<const int2*>(arc_idxs) + i);

        // two independent gather chains -> compiler interleaves (MLP x2)
        float r0 = eval_one(xt2.x, xc2.x, a2.x, vals, t_tbl, c_tbl, dims);
        float r1 = eval_one(xt2.y, xc2.y, a2.y, vals, t_tbl, c_tbl, dims);

        __stcs(reinterpret_cast<float2*>(out) + i, make_float2(r0, r1));
    } else {
        float x_t = __ldcs(x_t_arr + b0);
        float x_c = __ldcs(x_c_arr + b0);
        int   a   = __ldcs(arc_idxs + b0);
        float r   = eval_one(x_t, x_c, a, vals, t_tbl, c_tbl, dims);
        __stcs(out + b0, r);
    }
}

extern "C" void kernel_launch(void* const* d_in, const int* in_sizes, int n_in,
                              void* d_out, int out_size)
{
    const float* input_trans = (const float*)d_in[0];
    const float* output_caps = (const float*)d_in[1];
    const int*   arc_idxs    = (const int*)d_in[2];
    const float* vals        = (const float*)d_in[3];
    const float* t_tbl       = (const float*)d_in[4];
    const float* c_tbl       = (const float*)d_in[5];
    const int*   dims        = (const int*)d_in[6];
    float*       out         = (float*)d_out;

    int B = in_sizes[0];
    int threads = 256;
    int evals_per_block = threads * 2;
    int blocks = (B + evals_per_block - 1) / evals_per_block;
    timing_prop_kernel<<<blocks, threads>>>(input_trans, output_caps, arc_idxs,
                                            vals, t_tbl, c_tbl, dims, out, B);
}